// round 5
// baseline (speedup 1.0000x reference)
#include <cuda_runtime.h>
#include <cuda_bf16.h>

// Problem constants (from reference setup_inputs)
#define Bc 2
#define Tc 2048
#define Dc 1024
#define Nc 16
#define Lc 16
#define Cc 128                 // Tc / Lc
#define S_TOT (Bc*Dc*Nc)       // 32768 states
#define PQ_TOT (Cc*S_TOT)      // 4,194,304

// Scratch (static device arrays — no allocation allowed)
__device__ float g_P[PQ_TOT];
__device__ float g_Q[PQ_TOT];
__device__ float g_H0[PQ_TOT];

// ---------------------------------------------------------------------------
// Clip identity used throughout: A < 0  =>  max(dl*A, -10) = A * min(dl, -10/A)
// so the t-accumulation is W[n] = sum_t min(dl_t, thr_n) (1 MNMX + 1 FADD),
// and S[n] = A[n]*W[n] with the multiply hoisted out of the loop.
// ---------------------------------------------------------------------------

// ---------------------------------------------------------------------------
// Kernel A: per-chunk carry coefficients. Thread = (b,k,d, n-half): 8 n each.
//   P_k[n] = exp( A_n * W[n] )
//   Q_k[n] = frac0[n] * b0[n] * u0 * eA0[n]   (fw[0] = eA[0] since L>1)
// ---------------------------------------------------------------------------
__global__ __launch_bounds__(256) void pq_kernel(
    const float* __restrict__ u,
    const float* __restrict__ delta,
    const float* __restrict__ bmat,
    const float* __restrict__ Alog)
{
    int bx = blockIdx.x;
    int dblk = bx & 7;            // 8 d-blocks of 128
    int k    = (bx >> 3) & 127;
    int b    = bx >> 10;

    int tid   = threadIdx.x;
    int nhalf = tid & 1;          // n = nhalf*8 + i
    int dloc  = tid >> 1;         // 0..127
    int d     = dblk * 128 + dloc;

    float A[8], thr[8];
#pragma unroll
    for (int i = 0; i < 8; ++i) {
        A[i]   = -__expf(Alog[nhalf * 8 + i]);
        thr[i] = -10.0f / A[i];
    }

    int base_td = (b * Tc + k * Lc) * Dc + d;

    float W[8];
#pragma unroll
    for (int i = 0; i < 8; ++i) W[i] = 0.0f;

    float dl0 = 0.0f;
#pragma unroll
    for (int t = 0; t < Lc; ++t) {
        float dl = delta[base_td + t * Dc];
        if (t == 0) dl0 = dl;
#pragma unroll
        for (int i = 0; i < 8; ++i)
            W[i] += fminf(dl, thr[i]);
    }

    float u0 = u[base_td];
    const float4* b0p = reinterpret_cast<const float4*>(
        bmat + (size_t)base_td * Nc + nhalf * 8);

    int sbase = k * S_TOT + (b * Dc + d) * Nc + nhalf * 8;
    float4* Pp = reinterpret_cast<float4*>(g_P + sbase);
    float4* Qp = reinterpret_cast<float4*>(g_Q + sbase);

#pragma unroll
    for (int q = 0; q < 2; ++q) {
        float4 b0 = b0p[q];
        float bv[4] = {b0.x, b0.y, b0.z, b0.w};
        float Pv[4], Qv[4];
#pragma unroll
        for (int j = 0; j < 4; ++j) {
            int i = q * 4 + j;
            float invA = 1.0f / (A[i] + 1e-12f);
            Pv[j] = __expf(A[i] * W[i]);
            float da0 = A[i] * fminf(dl0, thr[i]);
            float eA0 = __expf(da0);
            float frac0 = (fabsf(da0) < 1e-4f) ? (da0 * invA) : (eA0 - 1.0f) * invA;
            Qv[j] = frac0 * bv[j] * u0 * eA0;
        }
        Pp[q] = make_float4(Pv[0], Pv[1], Pv[2], Pv[3]);
        Qp[q] = make_float4(Qv[0], Qv[1], Qv[2], Qv[3]);
    }
}

// ---------------------------------------------------------------------------
// Kernel B: serial scan over the 128 chunks per state.
//   h0[k] = h (state entering chunk k);  h <- h*P[k] + Q[k]
// ---------------------------------------------------------------------------
__global__ __launch_bounds__(256) void scan_kernel()
{
    int s = blockIdx.x * blockDim.x + threadIdx.x;
    float h = 0.0f;
    for (int kk = 0; kk < Cc; kk += 8) {
        float Pv[8], Qv[8];
#pragma unroll
        for (int j = 0; j < 8; ++j) {
            Pv[j] = g_P[(kk + j) * S_TOT + s];
            Qv[j] = g_Q[(kk + j) * S_TOT + s];
        }
#pragma unroll
        for (int j = 0; j < 8; ++j) {
            g_H0[(kk + j) * S_TOT + s] = h;
            h = fmaf(h, Pv[j], Qv[j]);
        }
    }
}

// ---------------------------------------------------------------------------
// Kernel C: main pass. Thread = (b,k,d, n-quad). No register tables:
//   phase 1 accumulates only Wtot[i]; phase 2 walks ps (ascending j) and
//   Wr (descending t_idx = 15-j) simultaneously, re-deriving min(dl,thr)
//   from two broadcast delta loads (second is L1-hot).
//   y[t_idx] = sum_n (h0*cumA[t_idx] + PS[j]) * c[t_idx], cumA = exp(A*Wr).
// ---------------------------------------------------------------------------
__global__ __launch_bounds__(256, 3) void main_kernel(
    const float* __restrict__ u,
    const float* __restrict__ delta,
    const float* __restrict__ bmat,
    const float* __restrict__ cmat,
    const float* __restrict__ Alog,
    float* __restrict__ y)
{
    int bx = blockIdx.x;
    int dblk = bx & 15;          // 16 d-blocks of 64
    int k    = (bx >> 4) & 127;  // chunk
    int b    = bx >> 11;         // batch

    int tid  = threadIdx.x;
    int ng   = tid & 3;          // n-quad: n = 4*ng .. 4*ng+3
    int dloc = tid >> 2;         // 0..63
    int d    = dblk * 64 + dloc;

    float A[4], invA[4], thr[4];
#pragma unroll
    for (int i = 0; i < 4; ++i) {
        A[i]    = -__expf(Alog[4 * ng + i]);
        invA[i] = 1.0f / (A[i] + 1e-12f);
        thr[i]  = -10.0f / A[i];
    }

    int base_td = (b * Tc + k * Lc) * Dc + d;

    // Phase 1: Wtot only (no tables)
    float Wr[4] = {0.0f, 0.0f, 0.0f, 0.0f};
#pragma unroll
    for (int t = 0; t < Lc; ++t) {
        float dl = delta[base_td + t * Dc];
#pragma unroll
        for (int i = 0; i < 4; ++i)
            Wr[i] += fminf(dl, thr[i]);
    }

    float4 h04 = *reinterpret_cast<const float4*>(
        g_H0 + k * S_TOT + (b * Dc + d) * Nc + 4 * ng);
    float h0[4] = {h04.x, h04.y, h04.z, h04.w};

    __shared__ float s_y[Lc * 64];

    float ps[4] = {0.0f, 0.0f, 0.0f, 0.0f};

#pragma unroll
    for (int j = 0; j < Lc; ++j) {
        int t_idx = Lc - 1 - j;
        float dl_m = delta[base_td + j * Dc];      // for bu/fw at j
        float dl_t = delta[base_td + t_idx * Dc];  // for Wr walk (L1-hot)
        float uu   = u[base_td + j * Dc];
        float4 b4 = *reinterpret_cast<const float4*>(
            bmat + (size_t)(base_td + j * Dc) * Nc + 4 * ng);
        float4 c4 = *reinterpret_cast<const float4*>(
            cmat + (size_t)(base_td + t_idx * Dc) * Nc + 4 * ng);
        float bv[4] = {b4.x, b4.y, b4.z, b4.w};
        float cv[4] = {c4.x, c4.y, c4.z, c4.w};

        float contrib = 0.0f;
#pragma unroll
        for (int i = 0; i < 4; ++i) {
            float cumA = __expf(A[i] * Wr[i]);     // cumprod(eA)[t_idx]
            Wr[i] -= fminf(dl_t, thr[i]);

            float da = A[i] * fminf(dl_m, thr[i]);
            float eA = __expf(da);
            float frac = (fabsf(da) < 1e-4f) ? (da * invA[i])
                                             : (eA - 1.0f) * invA[i];
            float bu = frac * bv[i] * uu;
            float fw = (j == Lc - 1) ? 1.0f : eA;  // folds at compile time
            ps[i] += bu * fw;                      // ps = PS[j]
            contrib = fmaf(fmaf(h0[i], cumA, ps[i]), cv[i], contrib);
        }
        // reduce over the 4 n-quad lanes (bits 0..1 of lane id)
        contrib += __shfl_xor_sync(0xffffffffu, contrib, 1, 32);
        contrib += __shfl_xor_sync(0xffffffffu, contrib, 2, 32);
        if (ng == 0) s_y[t_idx * 64 + dloc] = contrib;
    }
    __syncthreads();

    // coalesced y writes: 4 rows of 256
#pragma unroll
    for (int r = 0; r < 4; ++r) {
        int idx = tid + r * 256;
        int tt = idx >> 6;
        int dw = idx & 63;
        y[(b * Tc + k * Lc + tt) * Dc + dblk * 64 + dw] = s_y[idx];
    }
}

// ---------------------------------------------------------------------------
extern "C" void kernel_launch(void* const* d_in, const int* in_sizes, int n_in,
                              void* d_out, int out_size)
{
    const float* u     = (const float*)d_in[0];
    const float* delta = (const float*)d_in[1];
    const float* bmat  = (const float*)d_in[2];
    const float* cmat  = (const float*)d_in[3];
    const float* Alog  = (const float*)d_in[4];
    float* y = (float*)d_out;

    pq_kernel<<<Bc * Cc * 8, 256>>>(u, delta, bmat, Alog);
    scan_kernel<<<S_TOT / 256, 256>>>();
    main_kernel<<<Bc * Cc * 16, 256>>>(u, delta, bmat, cmat, Alog, y);
}